// round 13
// baseline (speedup 1.0000x reference)
#include <cuda_runtime.h>
#include <cuda_fp16.h>

#define N_NODES 50000
#define N_EDGES 1600000
#define N_LABEL 200000
#define IN_C    128
#define HID1    256
#define HID2    32

#define SCAN_BLK 1024
#define N_SCAN_BLOCKS ((N_NODES + SCAN_BLK - 1) / SCAN_BLK)   // 49
#define PACK_BLOCKS   (N_NODES * 32 / 256)                     // 6250
#define FILL_BLOCKS   ((N_EDGES / 4 + 255) / 256)              // 1563

// ---------------- device scratch ----------------
__device__ __align__(256) int    g_cnt   [N_NODES];
__device__ __align__(256) int    g_rowptr[N_NODES + 1];
__device__ __align__(256) int    g_cursor[N_NODES];
__device__ __align__(256) int    g_csrc  [N_EDGES];
__device__ __align__(256) int    g_bsum  [64];
__device__            int        g_scan_done;
__device__ __align__(256) float  g_dinv  [N_NODES];
__device__ __align__(256) __half g_xh    [N_NODES * IN_C];   // fp16 dinv*x
__device__ __align__(256) __half g_s1h   [N_NODES * IN_C];   // fp16 conv1 aggregate
__device__ __align__(256) __half g_h1h   [N_NODES * HID1];   // fp16 hidden
__device__ __align__(256) __half g_th    [N_NODES * HID2];   // fp16 dinv*(h1@W2)
__device__ __align__(256) float  g_z     [N_NODES * HID2];

// ---------------- tf32 helpers ----------------
__device__ __forceinline__ unsigned f2tf32(float f) {
    unsigned r;
    asm("cvt.rna.tf32.f32 %0, %1;" : "=r"(r) : "f"(f));
    return r;
}
__device__ __forceinline__ void mma_tf32(float* c, unsigned a0, unsigned a1,
                                         unsigned a2, unsigned a3,
                                         unsigned b0, unsigned b1) {
    asm volatile(
        "mma.sync.aligned.m16n8k8.row.col.f32.tf32.tf32.f32 "
        "{%0,%1,%2,%3}, {%4,%5,%6,%7}, {%8,%9}, {%0,%1,%2,%3};"
        : "+f"(c[0]), "+f"(c[1]), "+f"(c[2]), "+f"(c[3])
        : "r"(a0), "r"(a1), "r"(a2), "r"(a3), "r"(b0), "r"(b1));
}
__device__ __forceinline__ void h8_to_tf32(unsigned* dst, uint4 u) {
    float2 f0 = __half22float2(*(__half2*)&u.x);
    float2 f1 = __half22float2(*(__half2*)&u.y);
    float2 f2 = __half22float2(*(__half2*)&u.z);
    float2 f3 = __half22float2(*(__half2*)&u.w);
    dst[0] = f2tf32(f0.x); dst[1] = f2tf32(f0.y);
    dst[2] = f2tf32(f1.x); dst[3] = f2tf32(f1.y);
    dst[4] = f2tf32(f2.x); dst[5] = f2tf32(f2.y);
    dst[6] = f2tf32(f3.x); dst[7] = f2tf32(f3.y);
}
#define H2(u) (*(__half2*)&(u))

// ---------------- hist ----------------
__global__ void k_hist(const int* __restrict__ ei) {
    if (blockIdx.x == 0 && threadIdx.x == 0) g_scan_done = 0;
    int t = blockIdx.x * blockDim.x + threadIdx.x;
    if (t < N_EDGES / 4) {
        int4 d = ((const int4*)(ei + N_EDGES))[t];
        atomicAdd(&g_cnt[d.x], 1);
        atomicAdd(&g_cnt[d.y], 1);
        atomicAdd(&g_cnt[d.z], 1);
        atomicAdd(&g_cnt[d.w], 1);
    }
}

// ---------------- fused scan: 49 co-resident blocks + spin grid-barrier ----------------
__global__ void k_scan() {
    __shared__ int sh[SCAN_BLK];
    __shared__ int sh2[64];
    const int b = blockIdx.x, t = threadIdx.x;
    int i = b * SCAN_BLK + t;
    int v = (i < N_NODES) ? g_cnt[i] : 0;
    if (i < N_NODES) g_dinv[i] = rsqrtf((float)(v + 1));
    sh[t] = v;
    __syncthreads();
#pragma unroll
    for (int off = 1; off < SCAN_BLK; off <<= 1) {
        int tmp = (t >= off) ? sh[t - off] : 0;
        __syncthreads();
        sh[t] += tmp;
        __syncthreads();
    }
    int incl = sh[t];
    if (t == SCAN_BLK - 1) {
        g_bsum[b] = incl;
        __threadfence();
        atomicAdd(&g_scan_done, 1);
    }
    if (t == 0) {
        while (*(volatile int*)&g_scan_done < (int)gridDim.x) {}
    }
    __syncthreads();
    __threadfence();
    if (t < 64) sh2[t] = (t < (int)gridDim.x) ? *(volatile int*)&g_bsum[t] : 0;
    __syncthreads();
#pragma unroll
    for (int off = 1; off < 64; off <<= 1) {
        int tmp = (t >= off && t < 64) ? sh2[t - off] : 0;
        __syncthreads();
        if (t < 64) sh2[t] += tmp;
        __syncthreads();
    }
    int boff = (b > 0) ? sh2[b - 1] : 0;
    if (i < N_NODES) {
        int r = boff + incl - v;
        g_rowptr[i] = r;
        g_cursor[i] = r;
    }
    if (b == 0 && t == 0) g_rowptr[N_NODES] = N_EDGES;
}

// ---------------- fused pack + fill ----------------
__global__ void k_packfill(const float* __restrict__ x, const int* __restrict__ ei) {
    int bi = blockIdx.x;
    if (bi < PACK_BLOCKS) {
        int t = bi * 256 + threadIdx.x;
        int node = t >> 5;
        float di = g_dinv[node];
        float4 v = ((const float4*)x)[t];
        union { __half2 h[2]; uint2 u; } cv;
        cv.h[0] = __floats2half2_rn(di * v.x, di * v.y);
        cv.h[1] = __floats2half2_rn(di * v.z, di * v.w);
        ((uint2*)g_xh)[t] = cv.u;
    } else {
        int t = (bi - PACK_BLOCKS) * 256 + threadIdx.x;
        if (t < N_EDGES / 4) {
            int4 s = ((const int4*)ei)[t];
            int4 d = ((const int4*)(ei + N_EDGES))[t];
            int p0 = atomicAdd(&g_cursor[d.x], 1);
            int p1 = atomicAdd(&g_cursor[d.y], 1);
            int p2 = atomicAdd(&g_cursor[d.z], 1);
            int p3 = atomicAdd(&g_cursor[d.w], 1);
            g_csrc[p0] = s.x;
            g_csrc[p1] = s.y;
            g_csrc[p2] = s.z;
            g_csrc[p3] = s.w;
        }
    }
}

// ---------------- conv1 gather: unroll 8, depth-2 fp16 tree, fp32 accum ----------------
__global__ void k_agg1() {
    int w = (blockIdx.x * blockDim.x + threadIdx.x) >> 5;
    if (w >= N_NODES) return;
    int lane = threadIdx.x & 31;
    int beg = g_rowptr[w], end = g_rowptr[w + 1];
    const uint2* xv = (const uint2*)g_xh;

    float4 acc;
    {   // self loop
        uint2 u = xv[w * 32 + lane];
        float2 f0 = __half22float2(H2(u.x));
        float2 f1 = __half22float2(H2(u.y));
        acc = make_float4(f0.x, f0.y, f1.x, f1.y);
    }
    int j = beg;
    int pre = (4 - (j & 3)) & 3;
    if (pre > end - j) pre = end - j;
    for (int p = 0; p < pre; p++, j++) {
        uint2 u = xv[g_csrc[j] * 32 + lane];
        float2 f0 = __half22float2(H2(u.x));
        float2 f1 = __half22float2(H2(u.y));
        acc.x += f0.x; acc.y += f0.y; acc.z += f1.x; acc.w += f1.y;
    }
    // 8-edge main loop: 8 gathers in flight, depth-2 hadd2 tree
    for (; j + 7 < end; j += 8) {
        int4 ca = *(const int4*)&g_csrc[j];
        int4 cb = *(const int4*)&g_csrc[j + 4];
        uint2 u0 = xv[ca.x * 32 + lane];
        uint2 u1 = xv[ca.y * 32 + lane];
        uint2 u2 = xv[ca.z * 32 + lane];
        uint2 u3 = xv[ca.w * 32 + lane];
        uint2 u4 = xv[cb.x * 32 + lane];
        uint2 u5 = xv[cb.y * 32 + lane];
        uint2 u6 = xv[cb.z * 32 + lane];
        uint2 u7 = xv[cb.w * 32 + lane];
        __half2 s0x = __hadd2(H2(u0.x), H2(u1.x));
        __half2 s0y = __hadd2(H2(u0.y), H2(u1.y));
        __half2 s1x = __hadd2(H2(u2.x), H2(u3.x));
        __half2 s1y = __hadd2(H2(u2.y), H2(u3.y));
        __half2 s2x = __hadd2(H2(u4.x), H2(u5.x));
        __half2 s2y = __hadd2(H2(u4.y), H2(u5.y));
        __half2 s3x = __hadd2(H2(u6.x), H2(u7.x));
        __half2 s3y = __hadd2(H2(u6.y), H2(u7.y));
        __half2 t0x = __hadd2(s0x, s1x);
        __half2 t0y = __hadd2(s0y, s1y);
        __half2 t1x = __hadd2(s2x, s3x);
        __half2 t1y = __hadd2(s2y, s3y);
        float2 a0 = __half22float2(t0x), b0 = __half22float2(t0y);
        float2 a1 = __half22float2(t1x), b1 = __half22float2(t1y);
        acc.x += a0.x + a1.x;
        acc.y += a0.y + a1.y;
        acc.z += b0.x + b1.x;
        acc.w += b0.y + b1.y;
    }
    for (; j + 3 < end; j += 4) {
        int4 c4 = *(const int4*)&g_csrc[j];
        uint2 u0 = xv[c4.x * 32 + lane];
        uint2 u1 = xv[c4.y * 32 + lane];
        uint2 u2 = xv[c4.z * 32 + lane];
        uint2 u3 = xv[c4.w * 32 + lane];
        __half2 p0x = __hadd2(H2(u0.x), H2(u1.x));
        __half2 p0y = __hadd2(H2(u0.y), H2(u1.y));
        __half2 p1x = __hadd2(H2(u2.x), H2(u3.x));
        __half2 p1y = __hadd2(H2(u2.y), H2(u3.y));
        float2 a0 = __half22float2(p0x), b0 = __half22float2(p0y);
        float2 a1 = __half22float2(p1x), b1 = __half22float2(p1y);
        acc.x += a0.x + a1.x;
        acc.y += a0.y + a1.y;
        acc.z += b0.x + b1.x;
        acc.w += b0.y + b1.y;
    }
    for (; j < end; j++) {
        uint2 u = xv[g_csrc[j] * 32 + lane];
        float2 f0 = __half22float2(H2(u.x));
        float2 f1 = __half22float2(H2(u.y));
        acc.x += f0.x; acc.y += f0.y; acc.z += f1.x; acc.w += f1.y;
    }
    union { __half2 h[2]; uint2 u; } cv;
    cv.h[0] = __floats2half2_rn(acc.x, acc.y);
    cv.h[1] = __floats2half2_rn(acc.z, acc.w);
    ((uint2*)g_s1h)[w * 32 + lane] = cv.u;
}

// ---------------- GEMM1 (tf32 MMA): BN=128, grid.y=2 ----------------
#define G1_AS 36
#define G1_BS 136
__global__ void k_gemm1(const float* __restrict__ W, const float* __restrict__ b1) {
    __shared__ unsigned As[128 * G1_AS];
    __shared__ unsigned Bs[32 * G1_BS];
    const int tid   = threadIdx.x;
    const int tileM = blockIdx.x * 128;
    const int tileN = blockIdx.y * 128;
    const int warpId = tid >> 5, lane = tid & 31;
    const int warpM = warpId & 3, warpN = warpId >> 2;   // 4M x 2N, warp 32x64
    const int gid = lane >> 2, tg = lane & 3;

    float acc[2][8][4] = {};

    for (int k0 = 0; k0 < IN_C; k0 += 32) {
        // A tile 128x32 halves: 512 uint4 slots -> 2 per thread
#pragma unroll
        for (int i = 0; i < 2; i++) {
            int idx = tid + i * 256;
            int r   = idx >> 2;
            int c8  = (idx & 3) * 8;
            int grow = tileM + r;
            uint4 u = make_uint4(0u, 0u, 0u, 0u);
            if (grow < N_NODES) u = *(const uint4*)&g_s1h[grow * IN_C + k0 + c8];
            h8_to_tf32(&As[r * G1_AS + c8], u);
        }
        // B tile 32x128 floats: 4096 / 256 = 16/thread = 4 float4
#pragma unroll
        for (int i = 0; i < 4; i++) {
            int idx = tid + i * 256;
            int r   = idx >> 5;
            int c   = (idx & 31) * 4;
            float4 v = *(const float4*)&W[(k0 + r) * HID1 + tileN + c];
            unsigned* b = &Bs[r * G1_BS + c];
            b[0]=f2tf32(v.x); b[1]=f2tf32(v.y); b[2]=f2tf32(v.z); b[3]=f2tf32(v.w);
        }
        __syncthreads();
#pragma unroll
        for (int ks = 0; ks < 32; ks += 8) {
            unsigned a[2][4];
#pragma unroll
            for (int mt = 0; mt < 2; mt++) {
                int rb = warpM * 32 + mt * 16;
                a[mt][0] = As[(rb + gid    ) * G1_AS + ks + tg    ];
                a[mt][1] = As[(rb + gid + 8) * G1_AS + ks + tg    ];
                a[mt][2] = As[(rb + gid    ) * G1_AS + ks + tg + 4];
                a[mt][3] = As[(rb + gid + 8) * G1_AS + ks + tg + 4];
            }
#pragma unroll
            for (int nt = 0; nt < 8; nt++) {
                int cb = warpN * 64 + nt * 8;
                unsigned b0 = Bs[(ks + tg    ) * G1_BS + cb + gid];
                unsigned b1v= Bs[(ks + tg + 4) * G1_BS + cb + gid];
                mma_tf32(acc[0][nt], a[0][0], a[0][1], a[0][2], a[0][3], b0, b1v);
                mma_tf32(acc[1][nt], a[1][0], a[1][1], a[1][2], a[1][3], b0, b1v);
            }
        }
        __syncthreads();
    }

#pragma unroll
    for (int mt = 0; mt < 2; mt++) {
        int r0 = tileM + warpM * 32 + mt * 16 + gid;
        int r1 = r0 + 8;
        float d0 = (r0 < N_NODES) ? g_dinv[r0] : 0.f;
        float d1 = (r1 < N_NODES) ? g_dinv[r1] : 0.f;
#pragma unroll
        for (int nt = 0; nt < 8; nt++) {
            int c = tileN + warpN * 64 + nt * 8 + tg * 2;
            float bb0 = b1[c], bb1 = b1[c + 1];
            if (r0 < N_NODES) {
                __half2 o = __floats2half2_rn(
                    fmaxf(d0 * acc[mt][nt][0] + bb0, 0.f),
                    fmaxf(d0 * acc[mt][nt][1] + bb1, 0.f));
                ((__half2*)g_h1h)[(r0 * HID1 + c) >> 1] = o;
            }
            if (r1 < N_NODES) {
                __half2 o = __floats2half2_rn(
                    fmaxf(d1 * acc[mt][nt][2] + bb0, 0.f),
                    fmaxf(d1 * acc[mt][nt][3] + bb1, 0.f));
                ((__half2*)g_h1h)[(r1 * HID1 + c) >> 1] = o;
            }
        }
    }
}

// ---------------- GEMM2 (tf32 MMA, fp16 A): th = fp16(dinv*(h1@W2)) ----------------
#define G2_AS 36
#define G2_BS 72
__global__ void k_gemm2(const float* __restrict__ W2) {
    __shared__ unsigned As[128 * G2_AS];
    __shared__ unsigned Bs[32 * G2_BS];
    const int tid   = threadIdx.x;
    const int tileM = blockIdx.x * 128;
    const int warpId = tid >> 5, lane = tid & 31;
    const int gid = lane >> 2, tg = lane & 3;

    float acc[4][4] = {};

    for (int k0 = 0; k0 < HID1; k0 += 32) {
#pragma unroll
        for (int i = 0; i < 2; i++) {
            int idx = tid + i * 256;
            int r   = idx >> 2;
            int c8  = (idx & 3) * 8;
            int grow = tileM + r;
            uint4 u = make_uint4(0u, 0u, 0u, 0u);
            if (grow < N_NODES) u = *(const uint4*)&g_h1h[grow * HID1 + k0 + c8];
            h8_to_tf32(&As[r * G2_AS + c8], u);
        }
        {
            int r = tid >> 3;
            int c = (tid & 7) * 4;
            float4 v = *(const float4*)&W2[(k0 + r) * HID2 + c];
            unsigned* b = &Bs[r * G2_BS + c];
            b[0]=f2tf32(v.x); b[1]=f2tf32(v.y); b[2]=f2tf32(v.z); b[3]=f2tf32(v.w);
        }
        __syncthreads();
#pragma unroll
        for (int ks = 0; ks < 32; ks += 8) {
            int rb = warpId * 16;
            unsigned a0 = As[(rb + gid    ) * G2_AS + ks + tg    ];
            unsigned a1 = As[(rb + gid + 8) * G2_AS + ks + tg    ];
            unsigned a2 = As[(rb + gid    ) * G2_AS + ks + tg + 4];
            unsigned a3 = As[(rb + gid + 8) * G2_AS + ks + tg + 4];
#pragma unroll
            for (int nt = 0; nt < 4; nt++) {
                int cb = nt * 8;
                unsigned b0 = Bs[(ks + tg    ) * G2_BS + cb + gid];
                unsigned b1v= Bs[(ks + tg + 4) * G2_BS + cb + gid];
                mma_tf32(acc[nt], a0, a1, a2, a3, b0, b1v);
            }
        }
        __syncthreads();
    }

    int r0 = tileM + warpId * 16 + gid;
    int r1 = r0 + 8;
    float d0 = (r0 < N_NODES) ? g_dinv[r0] : 0.f;
    float d1 = (r1 < N_NODES) ? g_dinv[r1] : 0.f;
#pragma unroll
    for (int nt = 0; nt < 4; nt++) {
        int c = nt * 8 + tg * 2;
        if (r0 < N_NODES)
            ((__half2*)g_th)[r0 * 16 + (c >> 1)] =
                __floats2half2_rn(d0 * acc[nt][0], d0 * acc[nt][1]);
        if (r1 < N_NODES)
            ((__half2*)g_th)[r1 * 16 + (c >> 1)] =
                __floats2half2_rn(d1 * acc[nt][2], d1 * acc[nt][3]);
    }
}

// ---------------- conv2 gather + z: warp/node, 4 parallel edges x 8 lanes ----------------
__global__ void k_agg2(const float* __restrict__ b2) {
    int w = (blockIdx.x * blockDim.x + threadIdx.x) >> 5;
    if (w >= N_NODES) return;
    int lane = threadIdx.x & 31;
    int grp = lane >> 3, gl = lane & 7;
    int beg = g_rowptr[w], end = g_rowptr[w + 1];
    const uint2* tv = (const uint2*)g_th;

    float4 acc = make_float4(0.f, 0.f, 0.f, 0.f);
    if (grp == 0) {   // self loop handled by group 0
        uint2 u = tv[w * 8 + gl];
        float2 f0 = __half22float2(H2(u.x));
        float2 f1 = __half22float2(H2(u.y));
        acc = make_float4(f0.x, f0.y, f1.x, f1.y);
    }
    int j = beg;
    int pre = (4 - (j & 3)) & 3;
    if (pre > end - j) pre = end - j;
    if (grp < pre) {
        uint2 u = tv[g_csrc[j + grp] * 8 + gl];
        float2 f0 = __half22float2(H2(u.x));
        float2 f1 = __half22float2(H2(u.y));
        acc.x += f0.x; acc.y += f0.y; acc.z += f1.x; acc.w += f1.y;
    }
    j += pre;
    for (; j + 7 < end; j += 8) {
        int4 ca = *(const int4*)&g_csrc[j];
        int4 cb = *(const int4*)&g_csrc[j + 4];
        int s0 = (grp == 0) ? ca.x : (grp == 1) ? ca.y : (grp == 2) ? ca.z : ca.w;
        int s1 = (grp == 0) ? cb.x : (grp == 1) ? cb.y : (grp == 2) ? cb.z : cb.w;
        uint2 u0 = tv[s0 * 8 + gl];
        uint2 u1 = tv[s1 * 8 + gl];
        __half2 px = __hadd2(H2(u0.x), H2(u1.x));
        __half2 py = __hadd2(H2(u0.y), H2(u1.y));
        float2 f0 = __half22float2(px);
        float2 f1 = __half22float2(py);
        acc.x += f0.x; acc.y += f0.y; acc.z += f1.x; acc.w += f1.y;
    }
    if (j + 3 < end) {
        int4 ca = *(const int4*)&g_csrc[j];
        int s0 = (grp == 0) ? ca.x : (grp == 1) ? ca.y : (grp == 2) ? ca.z : ca.w;
        uint2 u = tv[s0 * 8 + gl];
        float2 f0 = __half22float2(H2(u.x));
        float2 f1 = __half22float2(H2(u.y));
        acc.x += f0.x; acc.y += f0.y; acc.z += f1.x; acc.w += f1.y;
        j += 4;
    }
    int rem = end - j;
    if (grp < rem) {
        uint2 u = tv[g_csrc[j + grp] * 8 + gl];
        float2 f0 = __half22float2(H2(u.x));
        float2 f1 = __half22float2(H2(u.y));
        acc.x += f0.x; acc.y += f0.y; acc.z += f1.x; acc.w += f1.y;
    }
    // reduce across the 4 groups (xor 8, 16)
    acc.x += __shfl_xor_sync(0xffffffffu, acc.x, 8);
    acc.y += __shfl_xor_sync(0xffffffffu, acc.y, 8);
    acc.z += __shfl_xor_sync(0xffffffffu, acc.z, 8);
    acc.w += __shfl_xor_sync(0xffffffffu, acc.w, 8);
    acc.x += __shfl_xor_sync(0xffffffffu, acc.x, 16);
    acc.y += __shfl_xor_sync(0xffffffffu, acc.y, 16);
    acc.z += __shfl_xor_sync(0xffffffffu, acc.z, 16);
    acc.w += __shfl_xor_sync(0xffffffffu, acc.w, 16);
    if (lane < 8) {
        float dw = g_dinv[w];
        float4 bb = ((const float4*)b2)[lane];
        float4 o = make_float4(dw * acc.x + bb.x, dw * acc.y + bb.y,
                               dw * acc.z + bb.z, dw * acc.w + bb.w);
        ((float4*)g_z)[w * 8 + lane] = o;
    }
}

// ---------------- decode ----------------
__global__ void k_decode(const int* __restrict__ eli, float* __restrict__ out) {
    int t = blockIdx.x * blockDim.x + threadIdx.x;
    int k = t >> 3;
    if (k >= N_LABEL) return;
    int lane = t & 7;
    int a = eli[k];
    int b = eli[N_LABEL + k];
    float4 za = ((const float4*)g_z)[a * 8 + lane];
    float4 zb = ((const float4*)g_z)[b * 8 + lane];
    float p = za.x * zb.x + za.y * zb.y + za.z * zb.z + za.w * zb.w;
    p += __shfl_xor_sync(0xffffffffu, p, 4);
    p += __shfl_xor_sync(0xffffffffu, p, 2);
    p += __shfl_xor_sync(0xffffffffu, p, 1);
    if (lane == 0) out[k] = p;
}

// ---------------- launch ----------------
extern "C" void kernel_launch(void* const* d_in, const int* in_sizes, int n_in,
                              void* d_out, int out_size) {
    const float* x   = (const float*)d_in[0];
    const int*   ei  = (const int*)d_in[1];     // int32 (JAX x64 disabled)
    const int*   eli = (const int*)d_in[2];
    const float* W1  = (const float*)d_in[3];
    const float* b1  = (const float*)d_in[4];
    const float* W2  = (const float*)d_in[5];
    const float* b2  = (const float*)d_in[6];
    float* out = (float*)d_out;
    (void)in_sizes; (void)n_in; (void)out_size;

    void* cnt_ptr = nullptr;
    cudaGetSymbolAddress(&cnt_ptr, g_cnt);
    cudaMemsetAsync(cnt_ptr, 0, N_NODES * sizeof(int));

    k_hist    <<<(N_EDGES / 4 + 255) / 256, 256>>>(ei);
    k_scan    <<<N_SCAN_BLOCKS, SCAN_BLK>>>();
    k_packfill<<<PACK_BLOCKS + FILL_BLOCKS, 256>>>(x, ei);

    k_agg1    <<<(N_NODES * 32 + 255) / 256, 256>>>();

    dim3 g1((N_NODES + 127) / 128, 2);
    k_gemm1   <<<g1, 256>>>(W1, b1);
    k_gemm2   <<<(N_NODES + 127) / 128, 256>>>(W2);

    k_agg2    <<<(N_NODES * 32 + 255) / 256, 256>>>(b2);
    k_decode  <<<(N_LABEL * 8 + 255) / 256, 256>>>(eli, out);
}

// round 14
// speedup vs baseline: 1.0387x; 1.0387x over previous
#include <cuda_runtime.h>
#include <cuda_fp16.h>

#define N_NODES 50000
#define N_EDGES 1600000
#define N_LABEL 200000
#define IN_C    128
#define HID1    256
#define HID2    32

#define SCAN_BLK 1024
#define N_SCAN_BLOCKS ((N_NODES + SCAN_BLK - 1) / SCAN_BLK)   // 49
#define PACK_BLOCKS   (N_NODES * 32 / 256)                     // 6250
#define FILL_BLOCKS   ((N_EDGES / 4 + 255) / 256)              // 1563

// ---------------- device scratch ----------------
__device__ __align__(256) int    g_cnt   [N_NODES];
__device__ __align__(256) int    g_rowptr[N_NODES + 1];
__device__ __align__(256) int    g_cursor[N_NODES];
__device__ __align__(256) int    g_csrc  [N_EDGES];
__device__ __align__(256) int    g_bsum  [64];
__device__            int        g_scan_done;
__device__ __align__(256) float  g_dinv  [N_NODES];
__device__ __align__(256) __half g_xh    [N_NODES * IN_C];   // fp16 dinv*x
__device__ __align__(256) __half g_s1h   [N_NODES * IN_C];   // fp16 conv1 aggregate
__device__ __align__(256) __half g_h1h   [N_NODES * HID1];   // fp16 hidden
__device__ __align__(256) __half g_th    [N_NODES * HID2];   // fp16 dinv*(h1@W2)
__device__ __align__(256) float  g_z     [N_NODES * HID2];

// ---------------- tf32 helpers ----------------
__device__ __forceinline__ unsigned f2tf32(float f) {
    unsigned r;
    asm("cvt.rna.tf32.f32 %0, %1;" : "=r"(r) : "f"(f));
    return r;
}
__device__ __forceinline__ void mma_tf32(float* c, unsigned a0, unsigned a1,
                                         unsigned a2, unsigned a3,
                                         unsigned b0, unsigned b1) {
    asm volatile(
        "mma.sync.aligned.m16n8k8.row.col.f32.tf32.tf32.f32 "
        "{%0,%1,%2,%3}, {%4,%5,%6,%7}, {%8,%9}, {%0,%1,%2,%3};"
        : "+f"(c[0]), "+f"(c[1]), "+f"(c[2]), "+f"(c[3])
        : "r"(a0), "r"(a1), "r"(a2), "r"(a3), "r"(b0), "r"(b1));
}
__device__ __forceinline__ void h8_to_tf32(unsigned* dst, uint4 u) {
    float2 f0 = __half22float2(*(__half2*)&u.x);
    float2 f1 = __half22float2(*(__half2*)&u.y);
    float2 f2 = __half22float2(*(__half2*)&u.z);
    float2 f3 = __half22float2(*(__half2*)&u.w);
    dst[0] = f2tf32(f0.x); dst[1] = f2tf32(f0.y);
    dst[2] = f2tf32(f1.x); dst[3] = f2tf32(f1.y);
    dst[4] = f2tf32(f2.x); dst[5] = f2tf32(f2.y);
    dst[6] = f2tf32(f3.x); dst[7] = f2tf32(f3.y);
}
#define H2(u) (*(__half2*)&(u))

// ---------------- hist ----------------
__global__ void k_hist(const int* __restrict__ ei) {
    if (blockIdx.x == 0 && threadIdx.x == 0) g_scan_done = 0;
    int t = blockIdx.x * blockDim.x + threadIdx.x;
    if (t < N_EDGES / 4) {
        int4 d = ((const int4*)(ei + N_EDGES))[t];
        atomicAdd(&g_cnt[d.x], 1);
        atomicAdd(&g_cnt[d.y], 1);
        atomicAdd(&g_cnt[d.z], 1);
        atomicAdd(&g_cnt[d.w], 1);
    }
}

// ---------------- fused scan ----------------
__global__ void k_scan() {
    __shared__ int sh[SCAN_BLK];
    __shared__ int sh2[64];
    const int b = blockIdx.x, t = threadIdx.x;
    int i = b * SCAN_BLK + t;
    int v = (i < N_NODES) ? g_cnt[i] : 0;
    if (i < N_NODES) g_dinv[i] = rsqrtf((float)(v + 1));
    sh[t] = v;
    __syncthreads();
#pragma unroll
    for (int off = 1; off < SCAN_BLK; off <<= 1) {
        int tmp = (t >= off) ? sh[t - off] : 0;
        __syncthreads();
        sh[t] += tmp;
        __syncthreads();
    }
    int incl = sh[t];
    if (t == SCAN_BLK - 1) {
        g_bsum[b] = incl;
        __threadfence();
        atomicAdd(&g_scan_done, 1);
    }
    if (t == 0) {
        while (*(volatile int*)&g_scan_done < (int)gridDim.x) {}
    }
    __syncthreads();
    __threadfence();
    if (t < 64) sh2[t] = (t < (int)gridDim.x) ? *(volatile int*)&g_bsum[t] : 0;
    __syncthreads();
#pragma unroll
    for (int off = 1; off < 64; off <<= 1) {
        int tmp = (t >= off && t < 64) ? sh2[t - off] : 0;
        __syncthreads();
        if (t < 64) sh2[t] += tmp;
        __syncthreads();
    }
    int boff = (b > 0) ? sh2[b - 1] : 0;
    if (i < N_NODES) {
        int r = boff + incl - v;
        g_rowptr[i] = r;
        g_cursor[i] = r;
    }
    if (b == 0 && t == 0) g_rowptr[N_NODES] = N_EDGES;
}

// ---------------- fused pack + fill ----------------
__global__ void k_packfill(const float* __restrict__ x, const int* __restrict__ ei) {
    int bi = blockIdx.x;
    if (bi < PACK_BLOCKS) {
        int t = bi * 256 + threadIdx.x;
        int node = t >> 5;
        float di = g_dinv[node];
        float4 v = ((const float4*)x)[t];
        union { __half2 h[2]; uint2 u; } cv;
        cv.h[0] = __floats2half2_rn(di * v.x, di * v.y);
        cv.h[1] = __floats2half2_rn(di * v.z, di * v.w);
        ((uint2*)g_xh)[t] = cv.u;
    } else {
        int t = (bi - PACK_BLOCKS) * 256 + threadIdx.x;
        if (t < N_EDGES / 4) {
            int4 s = ((const int4*)ei)[t];
            int4 d = ((const int4*)(ei + N_EDGES))[t];
            int p0 = atomicAdd(&g_cursor[d.x], 1);
            int p1 = atomicAdd(&g_cursor[d.y], 1);
            int p2 = atomicAdd(&g_cursor[d.z], 1);
            int p3 = atomicAdd(&g_cursor[d.w], 1);
            g_csrc[p0] = s.x;
            g_csrc[p1] = s.y;
            g_csrc[p2] = s.z;
            g_csrc[p3] = s.w;
        }
    }
}

// ---------------- conv1 gather: 16 lanes x uint4 per node, unroll 4, hadd2 tree
__global__ void k_agg1() {
    int t = blockIdx.x * blockDim.x + threadIdx.x;
    int w = t >> 4;
    if (w >= N_NODES) return;
    int lane = t & 15;                         // 16B lane within 256B row
    int beg = g_rowptr[w], end = g_rowptr[w + 1];
    const uint4* xv = (const uint4*)g_xh;      // 16 uint4 per row

    float acc[8];
    {   // self loop
        uint4 u = xv[w * 16 + lane];
        float2 f0 = __half22float2(H2(u.x));
        float2 f1 = __half22float2(H2(u.y));
        float2 f2 = __half22float2(H2(u.z));
        float2 f3 = __half22float2(H2(u.w));
        acc[0] = f0.x; acc[1] = f0.y; acc[2] = f1.x; acc[3] = f1.y;
        acc[4] = f2.x; acc[5] = f2.y; acc[6] = f3.x; acc[7] = f3.y;
    }
    int j = beg;
    int pre = (4 - (j & 3)) & 3;
    if (pre > end - j) pre = end - j;
    for (int p = 0; p < pre; p++, j++) {
        uint4 u = xv[g_csrc[j] * 16 + lane];
        float2 f0 = __half22float2(H2(u.x));
        float2 f1 = __half22float2(H2(u.y));
        float2 f2 = __half22float2(H2(u.z));
        float2 f3 = __half22float2(H2(u.w));
        acc[0] += f0.x; acc[1] += f0.y; acc[2] += f1.x; acc[3] += f1.y;
        acc[4] += f2.x; acc[5] += f2.y; acc[6] += f3.x; acc[7] += f3.y;
    }
    for (; j + 3 < end; j += 4) {
        int4 c4 = *(const int4*)&g_csrc[j];
        uint4 u0 = xv[c4.x * 16 + lane];
        uint4 u1 = xv[c4.y * 16 + lane];
        uint4 u2 = xv[c4.z * 16 + lane];
        uint4 u3 = xv[c4.w * 16 + lane];
        __half2 s0 = __hadd2(H2(u0.x), H2(u1.x));
        __half2 s1 = __hadd2(H2(u0.y), H2(u1.y));
        __half2 s2 = __hadd2(H2(u0.z), H2(u1.z));
        __half2 s3 = __hadd2(H2(u0.w), H2(u1.w));
        __half2 r0 = __hadd2(H2(u2.x), H2(u3.x));
        __half2 r1 = __hadd2(H2(u2.y), H2(u3.y));
        __half2 r2 = __hadd2(H2(u2.z), H2(u3.z));
        __half2 r3 = __hadd2(H2(u2.w), H2(u3.w));
        __half2 t0 = __hadd2(s0, r0);
        __half2 t1 = __hadd2(s1, r1);
        __half2 t2 = __hadd2(s2, r2);
        __half2 t3 = __hadd2(s3, r3);
        float2 f0 = __half22float2(t0);
        float2 f1 = __half22float2(t1);
        float2 f2 = __half22float2(t2);
        float2 f3 = __half22float2(t3);
        acc[0] += f0.x; acc[1] += f0.y; acc[2] += f1.x; acc[3] += f1.y;
        acc[4] += f2.x; acc[5] += f2.y; acc[6] += f3.x; acc[7] += f3.y;
    }
    for (; j < end; j++) {
        uint4 u = xv[g_csrc[j] * 16 + lane];
        float2 f0 = __half22float2(H2(u.x));
        float2 f1 = __half22float2(H2(u.y));
        float2 f2 = __half22float2(H2(u.z));
        float2 f3 = __half22float2(H2(u.w));
        acc[0] += f0.x; acc[1] += f0.y; acc[2] += f1.x; acc[3] += f1.y;
        acc[4] += f2.x; acc[5] += f2.y; acc[6] += f3.x; acc[7] += f3.y;
    }
    union { __half2 h[4]; uint4 u; } cv;
    cv.h[0] = __floats2half2_rn(acc[0], acc[1]);
    cv.h[1] = __floats2half2_rn(acc[2], acc[3]);
    cv.h[2] = __floats2half2_rn(acc[4], acc[5]);
    cv.h[3] = __floats2half2_rn(acc[6], acc[7]);
    ((uint4*)g_s1h)[w * 16 + lane] = cv.u;
}

// ---------------- GEMM1 (tf32 MMA, fp16 A): BN=64 (round-12 winner) ----------------
#define G1_AS 36
#define G1_BS 72
__global__ void k_gemm1(const float* __restrict__ W, const float* __restrict__ b1) {
    __shared__ unsigned As[128 * G1_AS];
    __shared__ unsigned Bs[32 * G1_BS];
    const int tid   = threadIdx.x;
    const int tileM = blockIdx.x * 128;
    const int tileN = blockIdx.y * 64;
    const int warpId = tid >> 5, lane = tid & 31;
    const int warpM = warpId & 3, warpN = warpId >> 2;
    const int gid = lane >> 2, tg = lane & 3;

    float acc[2][4][4] = {};

    for (int k0 = 0; k0 < IN_C; k0 += 32) {
#pragma unroll
        for (int i = 0; i < 2; i++) {
            int idx = tid + i * 256;
            int r   = idx >> 2;
            int c8  = (idx & 3) * 8;
            int grow = tileM + r;
            uint4 u = make_uint4(0u, 0u, 0u, 0u);
            if (grow < N_NODES) u = *(const uint4*)&g_s1h[grow * IN_C + k0 + c8];
            h8_to_tf32(&As[r * G1_AS + c8], u);
        }
#pragma unroll
        for (int i = 0; i < 2; i++) {
            int idx = tid + i * 256;
            int r   = idx >> 4;
            int c   = (idx & 15) * 4;
            float4 v = *(const float4*)&W[(k0 + r) * HID1 + tileN + c];
            unsigned* b = &Bs[r * G1_BS + c];
            b[0]=f2tf32(v.x); b[1]=f2tf32(v.y); b[2]=f2tf32(v.z); b[3]=f2tf32(v.w);
        }
        __syncthreads();
#pragma unroll
        for (int ks = 0; ks < 32; ks += 8) {
            unsigned a[2][4];
#pragma unroll
            for (int mt = 0; mt < 2; mt++) {
                int rb = warpM * 32 + mt * 16;
                a[mt][0] = As[(rb + gid    ) * G1_AS + ks + tg    ];
                a[mt][1] = As[(rb + gid + 8) * G1_AS + ks + tg    ];
                a[mt][2] = As[(rb + gid    ) * G1_AS + ks + tg + 4];
                a[mt][3] = As[(rb + gid + 8) * G1_AS + ks + tg + 4];
            }
#pragma unroll
            for (int nt = 0; nt < 4; nt++) {
                int cb = warpN * 32 + nt * 8;
                unsigned b0 = Bs[(ks + tg    ) * G1_BS + cb + gid];
                unsigned b1v= Bs[(ks + tg + 4) * G1_BS + cb + gid];
#pragma unroll
                for (int mt = 0; mt < 2; mt++)
                    mma_tf32(acc[mt][nt], a[mt][0], a[mt][1], a[mt][2], a[mt][3], b0, b1v);
            }
        }
        __syncthreads();
    }

#pragma unroll
    for (int mt = 0; mt < 2; mt++) {
        int r0 = tileM + warpM * 32 + mt * 16 + gid;
        int r1 = r0 + 8;
        float d0 = (r0 < N_NODES) ? g_dinv[r0] : 0.f;
        float d1 = (r1 < N_NODES) ? g_dinv[r1] : 0.f;
#pragma unroll
        for (int nt = 0; nt < 4; nt++) {
            int c = tileN + warpN * 32 + nt * 8 + tg * 2;
            float bb0 = b1[c], bb1 = b1[c + 1];
            if (r0 < N_NODES) {
                __half2 o = __floats2half2_rn(
                    fmaxf(d0 * acc[mt][nt][0] + bb0, 0.f),
                    fmaxf(d0 * acc[mt][nt][1] + bb1, 0.f));
                ((__half2*)g_h1h)[(r0 * HID1 + c) >> 1] = o;
            }
            if (r1 < N_NODES) {
                __half2 o = __floats2half2_rn(
                    fmaxf(d1 * acc[mt][nt][2] + bb0, 0.f),
                    fmaxf(d1 * acc[mt][nt][3] + bb1, 0.f));
                ((__half2*)g_h1h)[(r1 * HID1 + c) >> 1] = o;
            }
        }
    }
}

// ---------------- GEMM2 (tf32 MMA, fp16 A): th = fp16(dinv*(h1@W2)) ----------------
#define G2_AS 36
#define G2_BS 72
__global__ void k_gemm2(const float* __restrict__ W2) {
    __shared__ unsigned As[128 * G2_AS];
    __shared__ unsigned Bs[32 * G2_BS];
    const int tid   = threadIdx.x;
    const int tileM = blockIdx.x * 128;
    const int warpId = tid >> 5, lane = tid & 31;
    const int gid = lane >> 2, tg = lane & 3;

    float acc[4][4] = {};

    for (int k0 = 0; k0 < HID1; k0 += 32) {
#pragma unroll
        for (int i = 0; i < 2; i++) {
            int idx = tid + i * 256;
            int r   = idx >> 2;
            int c8  = (idx & 3) * 8;
            int grow = tileM + r;
            uint4 u = make_uint4(0u, 0u, 0u, 0u);
            if (grow < N_NODES) u = *(const uint4*)&g_h1h[grow * HID1 + k0 + c8];
            h8_to_tf32(&As[r * G2_AS + c8], u);
        }
        {
            int r = tid >> 3;
            int c = (tid & 7) * 4;
            float4 v = *(const float4*)&W2[(k0 + r) * HID2 + c];
            unsigned* b = &Bs[r * G2_BS + c];
            b[0]=f2tf32(v.x); b[1]=f2tf32(v.y); b[2]=f2tf32(v.z); b[3]=f2tf32(v.w);
        }
        __syncthreads();
#pragma unroll
        for (int ks = 0; ks < 32; ks += 8) {
            int rb = warpId * 16;
            unsigned a0 = As[(rb + gid    ) * G2_AS + ks + tg    ];
            unsigned a1 = As[(rb + gid + 8) * G2_AS + ks + tg    ];
            unsigned a2 = As[(rb + gid    ) * G2_AS + ks + tg + 4];
            unsigned a3 = As[(rb + gid + 8) * G2_AS + ks + tg + 4];
#pragma unroll
            for (int nt = 0; nt < 4; nt++) {
                int cb = nt * 8;
                unsigned b0 = Bs[(ks + tg    ) * G2_BS + cb + gid];
                unsigned b1v= Bs[(ks + tg + 4) * G2_BS + cb + gid];
                mma_tf32(acc[nt], a0, a1, a2, a3, b0, b1v);
            }
        }
        __syncthreads();
    }

    int r0 = tileM + warpId * 16 + gid;
    int r1 = r0 + 8;
    float d0 = (r0 < N_NODES) ? g_dinv[r0] : 0.f;
    float d1 = (r1 < N_NODES) ? g_dinv[r1] : 0.f;
#pragma unroll
    for (int nt = 0; nt < 4; nt++) {
        int c = nt * 8 + tg * 2;
        if (r0 < N_NODES)
            ((__half2*)g_th)[r0 * 16 + (c >> 1)] =
                __floats2half2_rn(d0 * acc[nt][0], d0 * acc[nt][1]);
        if (r1 < N_NODES)
            ((__half2*)g_th)[r1 * 16 + (c >> 1)] =
                __floats2half2_rn(d1 * acc[nt][2], d1 * acc[nt][3]);
    }
}

// ---------------- conv2 gather + z: 8 lanes/node (round-12 winner) ----------------
__global__ void k_agg2(const float* __restrict__ b2) {
    int t = blockIdx.x * blockDim.x + threadIdx.x;
    int w = t >> 3;
    if (w >= N_NODES) return;
    int lane = t & 7;
    int beg = g_rowptr[w], end = g_rowptr[w + 1];
    const uint2* tv = (const uint2*)g_th;

    float4 acc;
    {   // self loop
        uint2 u = tv[w * 8 + lane];
        float2 f0 = __half22float2(H2(u.x));
        float2 f1 = __half22float2(H2(u.y));
        acc = make_float4(f0.x, f0.y, f1.x, f1.y);
    }
    int j = beg;
    int pre = (4 - (j & 3)) & 3;
    if (pre > end - j) pre = end - j;
    for (int p = 0; p < pre; p++, j++) {
        uint2 u = tv[g_csrc[j] * 8 + lane];
        float2 f0 = __half22float2(H2(u.x));
        float2 f1 = __half22float2(H2(u.y));
        acc.x += f0.x; acc.y += f0.y; acc.z += f1.x; acc.w += f1.y;
    }
    for (; j + 3 < end; j += 4) {
        int4 c4 = *(const int4*)&g_csrc[j];
        uint2 u0 = tv[c4.x * 8 + lane];
        uint2 u1 = tv[c4.y * 8 + lane];
        uint2 u2 = tv[c4.z * 8 + lane];
        uint2 u3 = tv[c4.w * 8 + lane];
        __half2 p0x = __hadd2(H2(u0.x), H2(u1.x));
        __half2 p0y = __hadd2(H2(u0.y), H2(u1.y));
        __half2 p1x = __hadd2(H2(u2.x), H2(u3.x));
        __half2 p1y = __hadd2(H2(u2.y), H2(u3.y));
        float2 a0 = __half22float2(p0x), b0 = __half22float2(p0y);
        float2 a1 = __half22float2(p1x), b1 = __half22float2(p1y);
        acc.x += a0.x + a1.x;
        acc.y += a0.y + a1.y;
        acc.z += b0.x + b1.x;
        acc.w += b0.y + b1.y;
    }
    for (; j < end; j++) {
        uint2 u = tv[g_csrc[j] * 8 + lane];
        float2 f0 = __half22float2(H2(u.x));
        float2 f1 = __half22float2(H2(u.y));
        acc.x += f0.x; acc.y += f0.y; acc.z += f1.x; acc.w += f1.y;
    }
    float dw = g_dinv[w];
    float4 bb = ((const float4*)b2)[lane];
    float4 o = make_float4(dw * acc.x + bb.x, dw * acc.y + bb.y,
                           dw * acc.z + bb.z, dw * acc.w + bb.w);
    ((float4*)g_z)[w * 8 + lane] = o;
}

// ---------------- decode ----------------
__global__ void k_decode(const int* __restrict__ eli, float* __restrict__ out) {
    int t = blockIdx.x * blockDim.x + threadIdx.x;
    int k = t >> 3;
    if (k >= N_LABEL) return;
    int lane = t & 7;
    int a = eli[k];
    int b = eli[N_LABEL + k];
    float4 za = ((const float4*)g_z)[a * 8 + lane];
    float4 zb = ((const float4*)g_z)[b * 8 + lane];
    float p = za.x * zb.x + za.y * zb.y + za.z * zb.z + za.w * zb.w;
    p += __shfl_xor_sync(0xffffffffu, p, 4);
    p += __shfl_xor_sync(0xffffffffu, p, 2);
    p += __shfl_xor_sync(0xffffffffu, p, 1);
    if (lane == 0) out[k] = p;
}

// ---------------- launch ----------------
extern "C" void kernel_launch(void* const* d_in, const int* in_sizes, int n_in,
                              void* d_out, int out_size) {
    const float* x   = (const float*)d_in[0];
    const int*   ei  = (const int*)d_in[1];     // int32 (JAX x64 disabled)
    const int*   eli = (const int*)d_in[2];
    const float* W1  = (const float*)d_in[3];
    const float* b1  = (const float*)d_in[4];
    const float* W2  = (const float*)d_in[5];
    const float* b2  = (const float*)d_in[6];
    float* out = (float*)d_out;
    (void)in_sizes; (void)n_in; (void)out_size;

    void* cnt_ptr = nullptr;
    cudaGetSymbolAddress(&cnt_ptr, g_cnt);
    cudaMemsetAsync(cnt_ptr, 0, N_NODES * sizeof(int));

    k_hist    <<<(N_EDGES / 4 + 255) / 256, 256>>>(ei);
    k_scan    <<<N_SCAN_BLOCKS, SCAN_BLK>>>();
    k_packfill<<<PACK_BLOCKS + FILL_BLOCKS, 256>>>(x, ei);

    k_agg1    <<<(N_NODES * 16 + 255) / 256, 256>>>();

    dim3 g1((N_NODES + 127) / 128, HID1 / 64);
    k_gemm1   <<<g1, 256>>>(W1, b1);
    k_gemm2   <<<(N_NODES + 127) / 128, 256>>>(W2);

    k_agg2    <<<(N_NODES * 8 + 255) / 256, 256>>>(b2);
    k_decode  <<<(N_LABEL * 8 + 255) / 256, 256>>>(eli, out);
}